// round 1
// baseline (speedup 1.0000x reference)
#include <cuda_runtime.h>
#include <math.h>

#define D_MODEL 1024
#define NHEADS  16
#define DK      64
#define SEQ     2048
#define BATCH   2
#define NTOK    (BATCH*SEQ)   // 4096
#define DFF     4096

// ---------------- scratch (no allocations allowed) ----------------
__device__ float g_q  [NTOK*D_MODEL];
__device__ float g_k  [NTOK*D_MODEL];
__device__ float g_v  [NTOK*D_MODEL];
__device__ float g_ctx[NTOK*D_MODEL];
__device__ float g_s1 [NTOK*D_MODEL];
__device__ float g_x1 [NTOK*D_MODEL];
__device__ float g_ff [NTOK*DFF];
__device__ float g_s2 [NTOK*D_MODEL];

// ---------------- SGEMM: C[M,N] = A[M,K] @ B[K,N] (+ epilogue) ----------------
// EPI 1: store to head-transposed layout [B,H,S,DK] (for Q/K/V)
// EPI 2: C = acc + bias[n] + res[m*N+n]
// EPI 3: C = relu(acc + bias[n])
template<int EPI>
__global__ __launch_bounds__(256, 2)
void sgemm_k(const float* __restrict__ A, const float* __restrict__ B,
             float* __restrict__ C, const float* __restrict__ bias,
             const float* __restrict__ res, int M, int N, int K)
{
    __shared__ float sA[16*128];   // k-major (transposed A tile)
    __shared__ float sB[16*128];

    const int tid = threadIdx.x;
    const int bm = blockIdx.y, bn = blockIdx.x;
    const int ty = tid >> 4, tx = tid & 15;

    float acc[8][8];
#pragma unroll
    for (int i = 0; i < 8; i++)
#pragma unroll
        for (int j = 0; j < 8; j++) acc[i][j] = 0.f;

    const float* Ablk = A + (size_t)bm * 128 * K;
    const float* Bblk = B + (size_t)bn * 128;

    for (int k0 = 0; k0 < K; k0 += 16) {
        // load A tile (128 rows x 16 k), store transposed
#pragma unroll
        for (int t = 0; t < 2; t++) {
            int idx = t * 256 + tid;
            int arow = idx >> 2, akq = (idx & 3) << 2;
            float4 a = *(const float4*)(Ablk + (size_t)arow * K + k0 + akq);
            sA[(akq+0)*128 + arow] = a.x;
            sA[(akq+1)*128 + arow] = a.y;
            sA[(akq+2)*128 + arow] = a.z;
            sA[(akq+3)*128 + arow] = a.w;
            int brow = idx >> 5, bcol = (idx & 31) << 2;
            *(float4*)(sB + brow*128 + bcol) =
                *(const float4*)(Bblk + (size_t)(k0 + brow) * N + bcol);
        }
        __syncthreads();
#pragma unroll
        for (int kk = 0; kk < 16; kk++) {
            float4 a0 = *(float4*)(sA + kk*128 + ty*4);
            float4 a1 = *(float4*)(sA + kk*128 + 64 + ty*4);
            float4 b0 = *(float4*)(sB + kk*128 + tx*4);
            float4 b1 = *(float4*)(sB + kk*128 + 64 + tx*4);
            float av[8] = {a0.x,a0.y,a0.z,a0.w, a1.x,a1.y,a1.z,a1.w};
            float bv[8] = {b0.x,b0.y,b0.z,b0.w, b1.x,b1.y,b1.z,b1.w};
#pragma unroll
            for (int i = 0; i < 8; i++)
#pragma unroll
                for (int j = 0; j < 8; j++)
                    acc[i][j] = fmaf(av[i], bv[j], acc[i][j]);
        }
        __syncthreads();
    }

    // epilogue
    int rows[8], cols[8];
#pragma unroll
    for (int i = 0; i < 4; i++) {
        rows[i]   = bm*128 + ty*4 + i;
        rows[i+4] = bm*128 + 64 + ty*4 + i;
        cols[i]   = bn*128 + tx*4 + i;
        cols[i+4] = bn*128 + 64 + tx*4 + i;
    }
#pragma unroll
    for (int i = 0; i < 8; i++) {
        int r = rows[i];
#pragma unroll
        for (int j = 0; j < 8; j++) {
            int c = cols[j];
            float vacc = acc[i][j];
            if (EPI == 1) {
                int b = r >> 11, s = r & 2047;
                int h = c >> 6,  d = c & 63;
                C[(((size_t)b*NHEADS + h)*SEQ + s)*DK + d] = vacc;
            } else if (EPI == 2) {
                C[(size_t)r*N + c] = vacc + bias[c] + res[(size_t)r*N + c];
            } else { // 3
                float v = vacc + bias[c];
                C[(size_t)r*N + c] = v > 0.f ? v : 0.f;
            }
        }
    }
}

// ---------------- Flash attention (per b,h, 64-query tile) ----------------
__global__ __launch_bounds__(256)
void attn_kernel(const float* __restrict__ Q, const float* __restrict__ K,
                 const float* __restrict__ V, const int* __restrict__ mask,
                 float* __restrict__ ctx)
{
    extern __shared__ float sm[];
    float* Qt = sm;          // [64 d][64 q]
    float* Kt = sm + 4096;   // [64 d][64 kv], reused as Ps[q][kv]
    float* Vs = sm + 8192;   // [64 kv][64 d]

    const int tid = threadIdx.x;
    const int ty = tid >> 4, tx = tid & 15;
    const int qb = blockIdx.x;          // 0..31
    const int h  = blockIdx.y;
    const int b  = blockIdx.z;

    const size_t headoff = ((size_t)(b*NHEADS + h)) * SEQ * DK;
    const float* Qh = Q + headoff + (size_t)qb*64*DK;
    const float* Kh = K + headoff;
    const float* Vh = V + headoff;

    // load Q tile, transpose to d-major, fold in 1/sqrt(dk)
#pragma unroll
    for (int t = 0; t < 4; t++) {
        int idx = t*256 + tid;           // float4 units over 64x64
        int row = idx >> 4, c4 = (idx & 15) << 2;
        float4 qv = *(const float4*)(Qh + row*64 + c4);
        Qt[(c4+0)*64 + row] = qv.x * 0.125f;
        Qt[(c4+1)*64 + row] = qv.y * 0.125f;
        Qt[(c4+2)*64 + row] = qv.z * 0.125f;
        Qt[(c4+3)*64 + row] = qv.w * 0.125f;
    }

    float m_[4], l_[4], o_[4][4];
#pragma unroll
    for (int i = 0; i < 4; i++) {
        m_[i] = -1e30f; l_[i] = 0.f;
#pragma unroll
        for (int j = 0; j < 4; j++) o_[i][j] = 0.f;
    }

    for (int kv0 = 0; kv0 < SEQ; kv0 += 64) {
        // load K (transposed) and V (straight)
#pragma unroll
        for (int t = 0; t < 4; t++) {
            int idx = t*256 + tid;
            int row = idx >> 4, c4 = (idx & 15) << 2;
            float4 kvv = *(const float4*)(Kh + (size_t)(kv0+row)*64 + c4);
            Kt[(c4+0)*64 + row] = kvv.x;
            Kt[(c4+1)*64 + row] = kvv.y;
            Kt[(c4+2)*64 + row] = kvv.z;
            Kt[(c4+3)*64 + row] = kvv.w;
            *(float4*)(Vs + row*64 + c4) =
                *(const float4*)(Vh + (size_t)(kv0+row)*64 + c4);
        }
        __syncthreads();

        // S = Q K^T  (4x4 per thread)
        float s[4][4];
#pragma unroll
        for (int i = 0; i < 4; i++)
#pragma unroll
            for (int j = 0; j < 4; j++) s[i][j] = 0.f;
#pragma unroll
        for (int d = 0; d < 64; d++) {
            float4 qa = *(float4*)(Qt + d*64 + ty*4);
            float4 ka = *(float4*)(Kt + d*64 + tx*4);
            float qv[4] = {qa.x,qa.y,qa.z,qa.w};
            float kv[4] = {ka.x,ka.y,ka.z,ka.w};
#pragma unroll
            for (int i = 0; i < 4; i++)
#pragma unroll
                for (int j = 0; j < 4; j++)
                    s[i][j] = fmaf(qv[i], kv[j], s[i][j]);
        }
        // mask (all-ones in this dataset, but applied for correctness)
#pragma unroll
        for (int j = 0; j < 4; j++) {
            if (mask[b*SEQ + kv0 + tx*4 + j] == 0) {
                s[0][j] = -1e9f; s[1][j] = -1e9f; s[2][j] = -1e9f; s[3][j] = -1e9f;
            }
        }
        __syncthreads();               // Kt reads done -> reuse as Ps
        float* Ps = Kt;

        // online softmax (row owned by 16 lanes with same ty)
#pragma unroll
        for (int i = 0; i < 4; i++) {
            float mt = fmaxf(fmaxf(s[i][0], s[i][1]), fmaxf(s[i][2], s[i][3]));
#pragma unroll
            for (int off = 8; off; off >>= 1)
                mt = fmaxf(mt, __shfl_xor_sync(0xffffffffu, mt, off, 16));
            float mn = fmaxf(m_[i], mt);
            float p0 = __expf(s[i][0] - mn);
            float p1 = __expf(s[i][1] - mn);
            float p2 = __expf(s[i][2] - mn);
            float p3 = __expf(s[i][3] - mn);
            float rs = p0 + p1 + p2 + p3;
#pragma unroll
            for (int off = 8; off; off >>= 1)
                rs += __shfl_xor_sync(0xffffffffu, rs, off, 16);
            float f = __expf(m_[i] - mn);
            l_[i] = l_[i] * f + rs;
            m_[i] = mn;
#pragma unroll
            for (int j = 0; j < 4; j++) o_[i][j] *= f;
            *(float4*)(Ps + (ty*4 + i)*64 + tx*4) = make_float4(p0, p1, p2, p3);
        }
        __syncthreads();

        // O += P @ V
#pragma unroll
        for (int kv = 0; kv < 64; kv++) {
            float4 vv = *(float4*)(Vs + kv*64 + tx*4);
            float vvv[4] = {vv.x, vv.y, vv.z, vv.w};
            float pv[4];
#pragma unroll
            for (int i = 0; i < 4; i++) pv[i] = Ps[(ty*4 + i)*64 + kv];
#pragma unroll
            for (int i = 0; i < 4; i++)
#pragma unroll
                for (int j = 0; j < 4; j++)
                    o_[i][j] = fmaf(pv[i], vvv[j], o_[i][j]);
        }
        __syncthreads();
    }

    // write ctx in [B,S,D] layout
    const size_t obase = ((size_t)b*SEQ + (size_t)qb*64) * D_MODEL + h*DK;
#pragma unroll
    for (int i = 0; i < 4; i++) {
        float inv = 1.0f / l_[i];
        *(float4*)(ctx + obase + (size_t)(ty*4 + i)*D_MODEL + tx*4) =
            make_float4(o_[i][0]*inv, o_[i][1]*inv, o_[i][2]*inv, o_[i][3]*inv);
    }
}

// ---------------- LayerNorm (torch std: ddof=1, eps added to std) ----------------
__device__ __forceinline__ float warp_sum(float s) {
#pragma unroll
    for (int off = 16; off; off >>= 1) s += __shfl_xor_sync(0xffffffffu, s, off);
    return s;
}

__global__ __launch_bounds__(256)
void ln_kernel(const float* __restrict__ in, const float* __restrict__ alpha,
               const float* __restrict__ beta, float* __restrict__ out)
{
    __shared__ float red[8];
    const int row = blockIdx.x, tid = threadIdx.x;
    const float* rp = in + (size_t)row * D_MODEL;
    float4 v = *(const float4*)(rp + tid*4);

    float s = v.x + v.y + v.z + v.w;
    s = warp_sum(s);
    if ((tid & 31) == 0) red[tid >> 5] = s;
    __syncthreads();
    float tot = 0.f;
#pragma unroll
    for (int i = 0; i < 8; i++) tot += red[i];
    float mean = tot * (1.0f / 1024.0f);

    float dx = v.x - mean, dy = v.y - mean, dz = v.z - mean, dw = v.w - mean;
    float sq = dx*dx + dy*dy + dz*dz + dw*dw;
    __syncthreads();
    sq = warp_sum(sq);
    if ((tid & 31) == 0) red[tid >> 5] = sq;
    __syncthreads();
    float tot2 = 0.f;
#pragma unroll
    for (int i = 0; i < 8; i++) tot2 += red[i];
    float var  = tot2 * (1.0f / 1023.0f);     // ddof=1
    float rstd = 1.0f / (sqrtf(var) + 1e-6f); // eps added to std

    float4 a = *(const float4*)(alpha + tid*4);
    float4 bb = *(const float4*)(beta + tid*4);
    float4 o;
    o.x = a.x * dx * rstd + bb.x;
    o.y = a.y * dy * rstd + bb.y;
    o.z = a.z * dz * rstd + bb.z;
    o.w = a.w * dw * rstd + bb.w;
    *(float4*)(out + (size_t)row * D_MODEL + tid*4) = o;
}

// ---------------- host ----------------
extern "C" void kernel_launch(void* const* d_in, const int* in_sizes, int n_in,
                              void* d_out, int out_size)
{
    const float* x      = (const float*)d_in[0];
    const int*   mask   = (const int*)  d_in[1];
    const float* wq     = (const float*)d_in[2];
    const float* wk     = (const float*)d_in[3];
    const float* wv     = (const float*)d_in[4];
    const float* wo     = (const float*)d_in[5];
    const float* wo_b   = (const float*)d_in[6];
    const float* w1     = (const float*)d_in[7];
    const float* b1     = (const float*)d_in[8];
    const float* w2     = (const float*)d_in[9];
    const float* b2     = (const float*)d_in[10];
    const float* alpha1 = (const float*)d_in[11];
    const float* bias1  = (const float*)d_in[12];
    const float* alpha2 = (const float*)d_in[13];
    const float* bias2  = (const float*)d_in[14];
    float* out = (float*)d_out;

    float *q, *k, *v, *ctx, *s1, *x1, *ff, *s2;
    cudaGetSymbolAddress((void**)&q,   g_q);
    cudaGetSymbolAddress((void**)&k,   g_k);
    cudaGetSymbolAddress((void**)&v,   g_v);
    cudaGetSymbolAddress((void**)&ctx, g_ctx);
    cudaGetSymbolAddress((void**)&s1,  g_s1);
    cudaGetSymbolAddress((void**)&x1,  g_x1);
    cudaGetSymbolAddress((void**)&ff,  g_ff);
    cudaGetSymbolAddress((void**)&s2,  g_s2);

    dim3 blk(256);
    dim3 gD(D_MODEL/128, NTOK/128);      // (8, 32)
    dim3 gF(DFF/128, NTOK/128);          // (32, 32)

    // QKV projections (head-transposed outputs)
    sgemm_k<1><<<gD, blk>>>(x, wq, q, nullptr, nullptr, NTOK, D_MODEL, D_MODEL);
    sgemm_k<1><<<gD, blk>>>(x, wk, k, nullptr, nullptr, NTOK, D_MODEL, D_MODEL);
    sgemm_k<1><<<gD, blk>>>(x, wv, v, nullptr, nullptr, NTOK, D_MODEL, D_MODEL);

    // attention
    attn_kernel<<<dim3(SEQ/64, NHEADS, BATCH), blk, 3*4096*sizeof(float)>>>(q, k, v, mask, ctx);

    // O projection + residual, LN1
    sgemm_k<2><<<gD, blk>>>(ctx, wo, s1, wo_b, x, NTOK, D_MODEL, D_MODEL);
    ln_kernel<<<NTOK, 256>>>(s1, alpha1, bias1, x1);

    // FFN
    sgemm_k<3><<<gF, blk>>>(x1, w1, ff, b1, nullptr, NTOK, DFF, D_MODEL);
    sgemm_k<2><<<gD, blk>>>(ff, w2, s2, b2, x1, NTOK, D_MODEL, DFF);
    ln_kernel<<<NTOK, 256>>>(s2, alpha2, bias2, out);
}

// round 3
// speedup vs baseline: 1.1315x; 1.1315x over previous
#include <cuda_runtime.h>
#include <math.h>
#include <stdint.h>

#define D_MODEL 1024
#define NHEADS  16
#define DK      64
#define SEQ     2048
#define BATCH   2
#define NTOK    (BATCH*SEQ)   // 4096
#define DFF     4096

// ---------------- scratch (no allocations allowed) ----------------
__device__ float g_q  [NTOK*D_MODEL];
__device__ float g_k  [NTOK*D_MODEL];
__device__ float g_v  [NTOK*D_MODEL];
__device__ float g_ctx[NTOK*D_MODEL];
__device__ float g_s1 [NTOK*D_MODEL];
__device__ float g_x1 [NTOK*D_MODEL];
__device__ float g_ff [NTOK*DFF];
__device__ float g_s2 [NTOK*D_MODEL];

// ---------------- TF32 helpers ----------------
__device__ __forceinline__ uint32_t f2tf32(float x) {
    uint32_t r;
    asm("cvt.rna.tf32.f32 %0, %1;" : "=r"(r) : "f"(x));
    return r;
}
__device__ __forceinline__ void tf32_split(float x, uint32_t& hi, uint32_t& lo) {
    hi = f2tf32(x);
    lo = f2tf32(x - __uint_as_float(hi));
}
__device__ __forceinline__ void mma_16n8k8(float* d, const uint32_t* a, const uint32_t* b) {
    asm volatile(
        "mma.sync.aligned.m16n8k8.row.col.f32.tf32.tf32.f32 "
        "{%0,%1,%2,%3}, {%4,%5,%6,%7}, {%8,%9}, {%0,%1,%2,%3};\n"
        : "+f"(d[0]), "+f"(d[1]), "+f"(d[2]), "+f"(d[3])
        : "r"(a[0]), "r"(a[1]), "r"(a[2]), "r"(a[3]), "r"(b[0]), "r"(b[1]));
}

// ---------------- TF32x3 tensor-core GEMM ----------------
// C[M,N] = A[M,K] @ B[K,N]  (+ epilogue)
// EPI 1: store to head-transposed layout [B,H,S,DK] (for Q/K/V)
// EPI 2: C = acc + bias[n] + res[m*N+n]
// EPI 3: C = relu(acc + bias[n])
#define SA_STRIDE 20    // 16 k + 4 pad -> conflict-free fragment LDS
#define SB_STRIDE 136   // 128 n + 8 pad -> conflict-free fragment LDS

template<int EPI>
__global__ __launch_bounds__(256, 1)
void mma_gemm(const float* __restrict__ A, const float* __restrict__ B,
              float* __restrict__ C, const float* __restrict__ bias,
              const float* __restrict__ res, int M, int N, int K)
{
    __shared__ float sA[2][128 * SA_STRIDE];
    __shared__ float sB[2][16 * SB_STRIDE];

    const int tid  = threadIdx.x;
    const int lane = tid & 31;
    const int wid  = tid >> 5;
    const int g    = lane >> 2;      // group id (0..7)
    const int t    = lane & 3;       // thread-in-group (0..3)
    const int wm   = wid >> 2;       // 0..1  (m warp)
    const int wn   = wid & 3;        // 0..3  (n warp)
    const int bm   = blockIdx.y, bn = blockIdx.x;

    float c[4][4][4];                // [mt][nt][frag]
#pragma unroll
    for (int mt = 0; mt < 4; mt++)
#pragma unroll
        for (int nt = 0; nt < 4; nt++)
#pragma unroll
            for (int f = 0; f < 4; f++) c[mt][nt][f] = 0.f;

    auto prefetch = [&](int buf, int k0) {
#pragma unroll
        for (int it = 0; it < 2; it++) {
            int id = it * 256 + tid;
            // A tile: 128 rows x 16 k
            int ar = id >> 2, ak = (id & 3) << 2;
            const float* ga = A + (size_t)(bm * 128 + ar) * K + k0 + ak;
            uint32_t da = (uint32_t)__cvta_generic_to_shared(&sA[buf][ar * SA_STRIDE + ak]);
            asm volatile("cp.async.cg.shared.global [%0], [%1], 16;\n" :: "r"(da), "l"(ga));
            // B tile: 16 k x 128 n
            int br = id >> 5, bc = (id & 31) << 2;
            const float* gb = B + (size_t)(k0 + br) * N + bn * 128 + bc;
            uint32_t db = (uint32_t)__cvta_generic_to_shared(&sB[buf][br * SB_STRIDE + bc]);
            asm volatile("cp.async.cg.shared.global [%0], [%1], 16;\n" :: "r"(db), "l"(gb));
        }
        asm volatile("cp.async.commit_group;\n");
    };

    prefetch(0, 0);

    for (int k0 = 0; k0 < K; k0 += 16) {
        const int buf = (k0 >> 4) & 1;
        if (k0 + 16 < K) {
            prefetch(buf ^ 1, k0 + 16);
            asm volatile("cp.async.wait_group 1;\n");
        } else {
            asm volatile("cp.async.wait_group 0;\n");
        }
        __syncthreads();

#pragma unroll
        for (int ks = 0; ks < 16; ks += 8) {
            uint32_t ah[4][4], al[4][4];
#pragma unroll
            for (int mt = 0; mt < 4; mt++) {
                const float* pa = &sA[buf][(wm * 64 + mt * 16) * SA_STRIDE + ks];
                float x0 = pa[g * SA_STRIDE + t];
                float x1 = pa[(g + 8) * SA_STRIDE + t];
                float x2 = pa[g * SA_STRIDE + t + 4];
                float x3 = pa[(g + 8) * SA_STRIDE + t + 4];
                tf32_split(x0, ah[mt][0], al[mt][0]);
                tf32_split(x1, ah[mt][1], al[mt][1]);
                tf32_split(x2, ah[mt][2], al[mt][2]);
                tf32_split(x3, ah[mt][3], al[mt][3]);
            }
            uint32_t bh[4][2], bl[4][2];
#pragma unroll
            for (int nt = 0; nt < 4; nt++) {
                const float* pb = &sB[buf][ks * SB_STRIDE + wn * 32 + nt * 8 + g];
                float y0 = pb[t * SB_STRIDE];
                float y1 = pb[(t + 4) * SB_STRIDE];
                tf32_split(y0, bh[nt][0], bl[nt][0]);
                tf32_split(y1, bh[nt][1], bl[nt][1]);
            }
#pragma unroll
            for (int mt = 0; mt < 4; mt++)
#pragma unroll
                for (int nt = 0; nt < 4; nt++) {
                    mma_16n8k8(c[mt][nt], ah[mt], bh[nt]);   // hi*hi
                    mma_16n8k8(c[mt][nt], ah[mt], bl[nt]);   // hi*lo
                    mma_16n8k8(c[mt][nt], al[mt], bh[nt]);   // lo*hi
                }
        }
        __syncthreads();
    }

    // ---------------- epilogue ----------------
#pragma unroll
    for (int mt = 0; mt < 4; mt++) {
        const int r0 = bm * 128 + wm * 64 + mt * 16 + g;
#pragma unroll
        for (int nt = 0; nt < 4; nt++) {
            const int c0 = bn * 128 + wn * 32 + nt * 8 + t * 2;
#pragma unroll
            for (int half = 0; half < 2; half++) {
                const int r = r0 + half * 8;
#pragma unroll
                for (int e = 0; e < 2; e++) {
                    const int cc = c0 + e;
                    const float vacc = c[mt][nt][half * 2 + e];
                    if (EPI == 1) {
                        int b = r >> 11, s = r & 2047;
                        int h = cc >> 6, d = cc & 63;
                        C[(((size_t)b * NHEADS + h) * SEQ + s) * DK + d] = vacc;
                    } else if (EPI == 2) {
                        C[(size_t)r * N + cc] = vacc + bias[cc] + res[(size_t)r * N + cc];
                    } else {
                        float v = vacc + bias[cc];
                        C[(size_t)r * N + cc] = v > 0.f ? v : 0.f;
                    }
                }
            }
        }
    }
}

// ---------------- Flash attention (per b,h, 64-query tile) ----------------
__global__ __launch_bounds__(256)
void attn_kernel(const float* __restrict__ Q, const float* __restrict__ K,
                 const float* __restrict__ V, const int* __restrict__ mask,
                 float* __restrict__ ctx)
{
    extern __shared__ float sm[];
    float* Qt = sm;          // [64 d][64 q]
    float* Kt = sm + 4096;   // [64 d][64 kv], reused as Ps[q][kv]
    float* Vs = sm + 8192;   // [64 kv][64 d]

    const int tid = threadIdx.x;
    const int ty = tid >> 4, tx = tid & 15;
    const int qb = blockIdx.x;
    const int h  = blockIdx.y;
    const int b  = blockIdx.z;

    const size_t headoff = ((size_t)(b*NHEADS + h)) * SEQ * DK;
    const float* Qh = Q + headoff + (size_t)qb*64*DK;
    const float* Kh = K + headoff;
    const float* Vh = V + headoff;

#pragma unroll
    for (int t = 0; t < 4; t++) {
        int idx = t*256 + tid;
        int row = idx >> 4, c4 = (idx & 15) << 2;
        float4 qv = *(const float4*)(Qh + row*64 + c4);
        Qt[(c4+0)*64 + row] = qv.x * 0.125f;
        Qt[(c4+1)*64 + row] = qv.y * 0.125f;
        Qt[(c4+2)*64 + row] = qv.z * 0.125f;
        Qt[(c4+3)*64 + row] = qv.w * 0.125f;
    }

    float m_[4], l_[4], o_[4][4];
#pragma unroll
    for (int i = 0; i < 4; i++) {
        m_[i] = -1e30f; l_[i] = 0.f;
#pragma unroll
        for (int j = 0; j < 4; j++) o_[i][j] = 0.f;
    }

    for (int kv0 = 0; kv0 < SEQ; kv0 += 64) {
#pragma unroll
        for (int t = 0; t < 4; t++) {
            int idx = t*256 + tid;
            int row = idx >> 4, c4 = (idx & 15) << 2;
            float4 kvv = *(const float4*)(Kh + (size_t)(kv0+row)*64 + c4);
            Kt[(c4+0)*64 + row] = kvv.x;
            Kt[(c4+1)*64 + row] = kvv.y;
            Kt[(c4+2)*64 + row] = kvv.z;
            Kt[(c4+3)*64 + row] = kvv.w;
            *(float4*)(Vs + row*64 + c4) =
                *(const float4*)(Vh + (size_t)(kv0+row)*64 + c4);
        }
        __syncthreads();

        float s[4][4];
#pragma unroll
        for (int i = 0; i < 4; i++)
#pragma unroll
            for (int j = 0; j < 4; j++) s[i][j] = 0.f;
#pragma unroll
        for (int d = 0; d < 64; d++) {
            float4 qa = *(float4*)(Qt + d*64 + ty*4);
            float4 ka = *(float4*)(Kt + d*64 + tx*4);
            float qv[4] = {qa.x,qa.y,qa.z,qa.w};
            float kv[4] = {ka.x,ka.y,ka.z,ka.w};
#pragma unroll
            for (int i = 0; i < 4; i++)
#pragma unroll
                for (int j = 0; j < 4; j++)
                    s[i][j] = fmaf(qv[i], kv[j], s[i][j]);
        }
#pragma unroll
        for (int j = 0; j < 4; j++) {
            if (mask[b*SEQ + kv0 + tx*4 + j] == 0) {
                s[0][j] = -1e9f; s[1][j] = -1e9f; s[2][j] = -1e9f; s[3][j] = -1e9f;
            }
        }
        __syncthreads();
        float* Ps = Kt;

#pragma unroll
        for (int i = 0; i < 4; i++) {
            float mt = fmaxf(fmaxf(s[i][0], s[i][1]), fmaxf(s[i][2], s[i][3]));
#pragma unroll
            for (int off = 8; off; off >>= 1)
                mt = fmaxf(mt, __shfl_xor_sync(0xffffffffu, mt, off, 16));
            float mn = fmaxf(m_[i], mt);
            float p0 = __expf(s[i][0] - mn);
            float p1 = __expf(s[i][1] - mn);
            float p2 = __expf(s[i][2] - mn);
            float p3 = __expf(s[i][3] - mn);
            float rs = p0 + p1 + p2 + p3;
#pragma unroll
            for (int off = 8; off; off >>= 1)
                rs += __shfl_xor_sync(0xffffffffu, rs, off, 16);
            float f = __expf(m_[i] - mn);
            l_[i] = l_[i] * f + rs;
            m_[i] = mn;
#pragma unroll
            for (int j = 0; j < 4; j++) o_[i][j] *= f;
            *(float4*)(Ps + (ty*4 + i)*64 + tx*4) = make_float4(p0, p1, p2, p3);
        }
        __syncthreads();

#pragma unroll
        for (int kv = 0; kv < 64; kv++) {
            float4 vv = *(float4*)(Vs + kv*64 + tx*4);
            float vvv[4] = {vv.x, vv.y, vv.z, vv.w};
            float pv[4];
#pragma unroll
            for (int i = 0; i < 4; i++) pv[i] = Ps[(ty*4 + i)*64 + kv];
#pragma unroll
            for (int i = 0; i < 4; i++)
#pragma unroll
                for (int j = 0; j < 4; j++)
                    o_[i][j] = fmaf(pv[i], vvv[j], o_[i][j]);
        }
        __syncthreads();
    }

    const size_t obase = ((size_t)b*SEQ + (size_t)qb*64) * D_MODEL + h*DK;
#pragma unroll
    for (int i = 0; i < 4; i++) {
        float inv = 1.0f / l_[i];
        *(float4*)(ctx + obase + (size_t)(ty*4 + i)*D_MODEL + tx*4) =
            make_float4(o_[i][0]*inv, o_[i][1]*inv, o_[i][2]*inv, o_[i][3]*inv);
    }
}

// ---------------- LayerNorm (torch std: ddof=1, eps added to std) ----------------
__device__ __forceinline__ float warp_sum(float s) {
#pragma unroll
    for (int off = 16; off; off >>= 1) s += __shfl_xor_sync(0xffffffffu, s, off);
    return s;
}

__global__ __launch_bounds__(256)
void ln_kernel(const float* __restrict__ in, const float* __restrict__ alpha,
               const float* __restrict__ beta, float* __restrict__ out)
{
    __shared__ float red[8];
    const int row = blockIdx.x, tid = threadIdx.x;
    const float* rp = in + (size_t)row * D_MODEL;
    float4 v = *(const float4*)(rp + tid*4);

    float s = v.x + v.y + v.z + v.w;
    s = warp_sum(s);
    if ((tid & 31) == 0) red[tid >> 5] = s;
    __syncthreads();
    float tot = 0.f;
#pragma unroll
    for (int i = 0; i < 8; i++) tot += red[i];
    float mean = tot * (1.0f / 1024.0f);

    float dx = v.x - mean, dy = v.y - mean, dz = v.z - mean, dw = v.w - mean;
    float sq = dx*dx + dy*dy + dz*dz + dw*dw;
    __syncthreads();
    sq = warp_sum(sq);
    if ((tid & 31) == 0) red[tid >> 5] = sq;
    __syncthreads();
    float tot2 = 0.f;
#pragma unroll
    for (int i = 0; i < 8; i++) tot2 += red[i];
    float var  = tot2 * (1.0f / 1023.0f);
    float rstd = 1.0f / (sqrtf(var) + 1e-6f);

    float4 a = *(const float4*)(alpha + tid*4);
    float4 bb = *(const float4*)(beta + tid*4);
    float4 o;
    o.x = a.x * dx * rstd + bb.x;
    o.y = a.y * dy * rstd + bb.y;
    o.z = a.z * dz * rstd + bb.z;
    o.w = a.w * dw * rstd + bb.w;
    *(float4*)(out + (size_t)row * D_MODEL + tid*4) = o;
}

// ---------------- host ----------------
extern "C" void kernel_launch(void* const* d_in, const int* in_sizes, int n_in,
                              void* d_out, int out_size)
{
    const float* x      = (const float*)d_in[0];
    const int*   mask   = (const int*)  d_in[1];
    const float* wq     = (const float*)d_in[2];
    const float* wk     = (const float*)d_in[3];
    const float* wv     = (const float*)d_in[4];
    const float* wo     = (const float*)d_in[5];
    const float* wo_b   = (const float*)d_in[6];
    const float* w1     = (const float*)d_in[7];
    const float* b1     = (const float*)d_in[8];
    const float* w2     = (const float*)d_in[9];
    const float* b2     = (const float*)d_in[10];
    const float* alpha1 = (const float*)d_in[11];
    const float* bias1  = (const float*)d_in[12];
    const float* alpha2 = (const float*)d_in[13];
    const float* bias2  = (const float*)d_in[14];
    float* out = (float*)d_out;

    float *q, *k, *v, *ctx, *s1, *x1, *ff, *s2;
    cudaGetSymbolAddress((void**)&q,   g_q);
    cudaGetSymbolAddress((void**)&k,   g_k);
    cudaGetSymbolAddress((void**)&v,   g_v);
    cudaGetSymbolAddress((void**)&ctx, g_ctx);
    cudaGetSymbolAddress((void**)&s1,  g_s1);
    cudaGetSymbolAddress((void**)&x1,  g_x1);
    cudaGetSymbolAddress((void**)&ff,  g_ff);
    cudaGetSymbolAddress((void**)&s2,  g_s2);

    dim3 blk(256);
    dim3 gD(D_MODEL/128, NTOK/128);      // (8, 32)
    dim3 gF(DFF/128, NTOK/128);          // (32, 32)

    // QKV projections (head-transposed outputs)
    mma_gemm<1><<<gD, blk>>>(x, wq, q, nullptr, nullptr, NTOK, D_MODEL, D_MODEL);
    mma_gemm<1><<<gD, blk>>>(x, wk, k, nullptr, nullptr, NTOK, D_MODEL, D_MODEL);
    mma_gemm<1><<<gD, blk>>>(x, wv, v, nullptr, nullptr, NTOK, D_MODEL, D_MODEL);

    // attention
    attn_kernel<<<dim3(SEQ/64, NHEADS, BATCH), blk, 3*4096*sizeof(float)>>>(q, k, v, mask, ctx);

    // O projection + residual, LN1
    mma_gemm<2><<<gD, blk>>>(ctx, wo, s1, wo_b, x, NTOK, D_MODEL, D_MODEL);
    ln_kernel<<<NTOK, 256>>>(s1, alpha1, bias1, x1);

    // FFN
    mma_gemm<3><<<gF, blk>>>(x1, w1, ff, b1, nullptr, NTOK, DFF, D_MODEL);
    mma_gemm<2><<<gD, blk>>>(ff, w2, s2, b2, x1, NTOK, D_MODEL, DFF);
    ln_kernel<<<NTOK, 256>>>(s2, alpha2, bias2, out);
}

// round 6
// speedup vs baseline: 1.4722x; 1.3010x over previous
#include <cuda_runtime.h>
#include <cuda_bf16.h>
#include <math.h>
#include <stdint.h>

#define D_MODEL 1024
#define NHEADS  16
#define DK      64
#define SEQ     2048
#define BATCH   2
#define NTOK    (BATCH*SEQ)   // 4096
#define DFF     4096

// ---------------- scratch (no allocations allowed) ----------------
__device__ float g_qkv[3*NTOK*D_MODEL];
__device__ float g_ctx[NTOK*D_MODEL];
__device__ float g_s1 [NTOK*D_MODEL];
__device__ float g_x1 [NTOK*D_MODEL];
__device__ float g_ff [NTOK*DFF];
__device__ float g_s2 [NTOK*D_MODEL];

// pre-split transposed weights [N][K], bf16 hi/lo
__device__ __nv_bfloat16 g_wqkv_hi[3*D_MODEL*D_MODEL];
__device__ __nv_bfloat16 g_wqkv_lo[3*D_MODEL*D_MODEL];
__device__ __nv_bfloat16 g_wo_hi  [D_MODEL*D_MODEL];
__device__ __nv_bfloat16 g_wo_lo  [D_MODEL*D_MODEL];
__device__ __nv_bfloat16 g_w1_hi  [DFF*D_MODEL];
__device__ __nv_bfloat16 g_w1_lo  [DFF*D_MODEL];
__device__ __nv_bfloat16 g_w2_hi  [D_MODEL*DFF];
__device__ __nv_bfloat16 g_w2_lo  [D_MODEL*DFF];

// ---------------- helpers ----------------
__device__ __forceinline__ uint32_t smem_u32(const void* p) {
    uint32_t a;
    asm("{ .reg .u64 t; cvta.to.shared.u64 t, %1; cvt.u32.u64 %0, t; }" : "=r"(a) : "l"(p));
    return a;
}
__device__ __forceinline__ void ldsm4(uint32_t* r, uint32_t addr) {
    asm volatile("ldmatrix.sync.aligned.m8n8.x4.shared.b16 {%0,%1,%2,%3}, [%4];"
        : "=r"(r[0]), "=r"(r[1]), "=r"(r[2]), "=r"(r[3]) : "r"(addr));
}
__device__ __forceinline__ void mma_bf16(float* d, const uint32_t* a, const uint32_t* b) {
    asm volatile(
        "mma.sync.aligned.m16n8k16.row.col.f32.bf16.bf16.f32 "
        "{%0,%1,%2,%3}, {%4,%5,%6,%7}, {%8,%9}, {%0,%1,%2,%3};"
        : "+f"(d[0]), "+f"(d[1]), "+f"(d[2]), "+f"(d[3])
        : "r"(a[0]), "r"(a[1]), "r"(a[2]), "r"(a[3]), "r"(b[0]), "r"(b[1]));
}
__device__ __forceinline__ uint32_t packbf2(float x, float y) {
    __nv_bfloat162 h = __floats2bfloat162_rn(x, y);
    return *(uint32_t*)&h;
}

// ---------------- weight prep: W[K][N] fp32 -> T[N][K] bf16 hi/lo ----------------
__global__ void prep_w(const float* __restrict__ W, __nv_bfloat16* __restrict__ Thi,
                       __nv_bfloat16* __restrict__ Tlo, int K, int N)
{
    __shared__ float t[32][33];
    const int k0 = blockIdx.y * 32, n0 = blockIdx.x * 32;
    const int tx = threadIdx.x, ty = threadIdx.y;   // 32 x 8
#pragma unroll
    for (int r = 0; r < 4; r++)
        t[ty + 8*r][tx] = W[(size_t)(k0 + ty + 8*r) * N + n0 + tx];
    __syncthreads();
#pragma unroll
    for (int r = 0; r < 4; r++) {
        const int n = n0 + ty + 8*r, k = k0 + tx;
        float x = t[tx][ty + 8*r];
        __nv_bfloat16 hi = __float2bfloat16(x);
        __nv_bfloat16 lo = __float2bfloat16(x - __bfloat162float(hi));
        Thi[(size_t)n * K + k] = hi;
        Tlo[(size_t)n * K + k] = lo;
    }
}

// ---------------- bf16x3 mma.sync GEMM: C[M,N] = A[M,K] @ Bt[N,K]^T ----------------
// Block 128x128, BK=32, 8 warps (2m x 4n), warp tile 64x32.
// smem per buffer: Ahi/Alo/Bhi/Blo each [128 rows][32 bf16] padded to 40 bf16 (80B) = 10240B
// EPI 1: store to g_qkv [3][B,H,S,DK]   EPI 2: +bias[n]+res   EPI 3: relu(+bias[n])
#define GS_BUF   40960                 // 4 * 10240
#define GS_AH    0
#define GS_AL    10240
#define GS_BH    20480
#define GS_BL    30720
#define SMEM_G   (2*GS_BUF)            // 81920

template<int EPI>
__global__ __launch_bounds__(256, 1)
void bf16_gemm(const float* __restrict__ A,
               const __nv_bfloat16* __restrict__ Bhi, const __nv_bfloat16* __restrict__ Blo,
               float* __restrict__ C, const float* __restrict__ bias,
               const float* __restrict__ res, int N, int K)
{
    extern __shared__ char smem[];
    const uint32_t sbase = smem_u32(smem);
    const int tid = threadIdx.x, wid = tid >> 5, lane = tid & 31;
    const int g = lane >> 2, t = lane & 3;
    const int wm = wid >> 2, wn = wid & 3;
    const int bm = blockIdx.y, bn = blockIdx.x;

    float c[4][4][4];
#pragma unroll
    for (int mt = 0; mt < 4; mt++)
#pragma unroll
        for (int nt = 0; nt < 4; nt++)
#pragma unroll
            for (int f = 0; f < 4; f++) c[mt][nt][f] = 0.f;

    // A load assignment: row = tid>>1 (0..127), half = tid&1 (16 k each)
    const int arow = tid >> 1, ahalf = tid & 1;
    const float* gA = A + (size_t)(bm * 128 + arow) * K + ahalf * 16;

    // B cp.async assignment: 4 chunks of 16B per thread
    auto cp_B = [&](int buf, int kb) {
#pragma unroll
        for (int j = 0; j < 4; j++) {
            const int cidx = tid + 256 * j;
            const int isLo = cidx >> 9;
            const int row  = (cidx >> 2) & 127;
            const int kc   = cidx & 3;
            const __nv_bfloat16* src = (isLo ? Blo : Bhi)
                + (size_t)(bn * 128 + row) * K + kb * 32 + kc * 8;
            const uint32_t dst = sbase + buf * GS_BUF + (isLo ? GS_BL : GS_BH)
                + row * 80 + kc * 16;
            asm volatile("cp.async.cg.shared.global [%0], [%1], 16;\n" :: "r"(dst), "l"(src));
        }
        asm volatile("cp.async.commit_group;\n");
    };

    float4 areg[4];
    auto load_A = [&](int kb) {
        const float* p = gA + kb * 32;
#pragma unroll
        for (int i = 0; i < 4; i++) areg[i] = *(const float4*)(p + 4 * i);
    };
    auto store_A = [&](int buf) {
        char* base = smem + buf * GS_BUF;
        const int off = arow * 80 + ahalf * 32;
        uint32_t* ph = (uint32_t*)(base + GS_AH + off);
        uint32_t* pl = (uint32_t*)(base + GS_AL + off);
#pragma unroll
        for (int i = 0; i < 4; i++) {
            float v0 = (i & 1) ? areg[i >> 1].z : areg[i >> 1].x;
            (void)v0;
        }
        // unpack: areg[i] holds floats 4i..4i+3
#pragma unroll
        for (int i = 0; i < 4; i++) {
            float f0 = areg[i].x, f1 = areg[i].y, f2 = areg[i].z, f3 = areg[i].w;
            __nv_bfloat16 h0 = __float2bfloat16(f0), h1 = __float2bfloat16(f1);
            __nv_bfloat16 h2 = __float2bfloat16(f2), h3 = __float2bfloat16(f3);
            float l0 = f0 - __bfloat162float(h0), l1 = f1 - __bfloat162float(h1);
            float l2 = f2 - __bfloat162float(h2), l3 = f3 - __bfloat162float(h3);
            __nv_bfloat162 hp0 = __nv_bfloat162(h0, h1), hp1 = __nv_bfloat162(h2, h3);
            ph[2*i]   = *(uint32_t*)&hp0;
            ph[2*i+1] = *(uint32_t*)&hp1;
            pl[2*i]   = packbf2(l0, l1);
            pl[2*i+1] = packbf2(l2, l3);
        }
    };

    // ldmatrix per-thread address components (bytes)
    const uint32_t a_off = (uint32_t)((wm * 64 + (lane & 15)) * 80 + ((lane >> 4) << 4));
    const uint32_t b_off = (uint32_t)((wn * 32 + ((lane >> 4) << 3) + (lane & 7)) * 80
                                      + (((lane >> 3) & 1) << 4));

    const int niter = K >> 5;
    load_A(0);
    cp_B(0, 0);
    store_A(0);
    asm volatile("cp.async.wait_group 0;\n");
    __syncthreads();

    for (int it = 0; it < niter; it++) {
        const int buf = it & 1;
        if (it + 1 < niter) { load_A(it + 1); cp_B(buf ^ 1, it + 1); }

        const uint32_t sb = sbase + buf * GS_BUF;
#pragma unroll
        for (int ks = 0; ks < 2; ks++) {
            uint32_t Ah[4][4], Al[4][4], Bh[2][4], Bl[2][4];
#pragma unroll
            for (int mt = 0; mt < 4; mt++) {
                const uint32_t aa = sb + a_off + mt * (16 * 80) + ks * 32;
                ldsm4(Ah[mt], aa + GS_AH);
                ldsm4(Al[mt], aa + GS_AL);
            }
#pragma unroll
            for (int ng = 0; ng < 2; ng++) {
                const uint32_t ba = sb + b_off + ng * (16 * 80) + ks * 32;
                ldsm4(Bh[ng], ba + GS_BH);
                ldsm4(Bl[ng], ba + GS_BL);
            }
#pragma unroll
            for (int mt = 0; mt < 4; mt++)
#pragma unroll
                for (int nt = 0; nt < 4; nt++) {
                    const uint32_t* bh = &Bh[nt >> 1][(nt & 1) * 2];
                    const uint32_t* bl = &Bl[nt >> 1][(nt & 1) * 2];
                    mma_bf16(c[mt][nt], Ah[mt], bh);   // hi*hi
                    mma_bf16(c[mt][nt], Ah[mt], bl);   // hi*lo
                    mma_bf16(c[mt][nt], Al[mt], bh);   // lo*hi
                }
        }

        if (it + 1 < niter) {
            store_A(buf ^ 1);
            asm volatile("cp.async.wait_group 0;\n");
        }
        __syncthreads();
    }

    // ---------------- epilogue ----------------
#pragma unroll
    for (int mt = 0; mt < 4; mt++) {
        const int r0 = bm * 128 + wm * 64 + mt * 16 + g;
#pragma unroll
        for (int nt = 0; nt < 4; nt++) {
            const int c0 = bn * 128 + wn * 32 + nt * 8 + t * 2;
#pragma unroll
            for (int half = 0; half < 2; half++) {
                const int r = r0 + half * 8;
#pragma unroll
                for (int e = 0; e < 2; e++) {
                    const int cc = c0 + e;
                    const float vacc = c[mt][nt][half * 2 + e];
                    if (EPI == 1) {
                        const int which = cc >> 10, cm = cc & 1023;
                        const int b = r >> 11, s = r & 2047;
                        C[(size_t)which * (NTOK * D_MODEL)
                          + (((size_t)(b * NHEADS + (cm >> 6)) * SEQ + s) * DK + (cm & 63))] = vacc;
                    } else if (EPI == 2) {
                        C[(size_t)r * N + cc] = vacc + bias[cc] + res[(size_t)r * N + cc];
                    } else {
                        float v = vacc + bias[cc];
                        C[(size_t)r * N + cc] = v > 0.f ? v : 0.f;
                    }
                }
            }
        }
    }
}

// ---------------- Flash attention (per b,h, 64-query tile) — R3-passing version ----------------
__global__ __launch_bounds__(256)
void attn_kernel(const float* __restrict__ Q, const float* __restrict__ K,
                 const float* __restrict__ V, const int* __restrict__ mask,
                 float* __restrict__ ctx)
{
    extern __shared__ float sm[];
    float* Qt = sm;
    float* Kt = sm + 4096;
    float* Vs = sm + 8192;

    const int tid = threadIdx.x;
    const int ty = tid >> 4, tx = tid & 15;
    const int qb = blockIdx.x;
    const int h  = blockIdx.y;
    const int b  = blockIdx.z;

    const size_t headoff = ((size_t)(b*NHEADS + h)) * SEQ * DK;
    const float* Qh = Q + headoff + (size_t)qb*64*DK;
    const float* Kh = K + headoff;
    const float* Vh = V + headoff;

#pragma unroll
    for (int tt = 0; tt < 4; tt++) {
        int idx = tt*256 + tid;
        int row = idx >> 4, c4 = (idx & 15) << 2;
        float4 qv = *(const float4*)(Qh + row*64 + c4);
        Qt[(c4+0)*64 + row] = qv.x * 0.125f;
        Qt[(c4+1)*64 + row] = qv.y * 0.125f;
        Qt[(c4+2)*64 + row] = qv.z * 0.125f;
        Qt[(c4+3)*64 + row] = qv.w * 0.125f;
    }

    float m_[4], l_[4], o_[4][4];
#pragma unroll
    for (int i = 0; i < 4; i++) {
        m_[i] = -1e30f; l_[i] = 0.f;
#pragma unroll
        for (int j = 0; j < 4; j++) o_[i][j] = 0.f;
    }

    for (int kv0 = 0; kv0 < SEQ; kv0 += 64) {
#pragma unroll
        for (int tt = 0; tt < 4; tt++) {
            int idx = tt*256 + tid;
            int row = idx >> 4, c4 = (idx & 15) << 2;
            float4 kvv = *(const float4*)(Kh + (size_t)(kv0+row)*64 + c4);
            Kt[(c4+0)*64 + row] = kvv.x;
            Kt[(c4+1)*64 + row] = kvv.y;
            Kt[(c4+2)*64 + row] = kvv.z;
            Kt[(c4+3)*64 + row] = kvv.w;
            *(float4*)(Vs + row*64 + c4) =
                *(const float4*)(Vh + (size_t)(kv0+row)*64 + c4);
        }
        __syncthreads();

        float s[4][4];
#pragma unroll
        for (int i = 0; i < 4; i++)
#pragma unroll
            for (int j = 0; j < 4; j++) s[i][j] = 0.f;
#pragma unroll
        for (int d = 0; d < 64; d++) {
            float4 qa = *(float4*)(Qt + d*64 + ty*4);
            float4 ka = *(float4*)(Kt + d*64 + tx*4);
            float qv[4] = {qa.x,qa.y,qa.z,qa.w};
            float kv[4] = {ka.x,ka.y,ka.z,ka.w};
#pragma unroll
            for (int i = 0; i < 4; i++)
#pragma unroll
                for (int j = 0; j < 4; j++)
                    s[i][j] = fmaf(qv[i], kv[j], s[i][j]);
        }
#pragma unroll
        for (int j = 0; j < 4; j++) {
            if (mask[b*SEQ + kv0 + tx*4 + j] == 0) {
                s[0][j] = -1e9f; s[1][j] = -1e9f; s[2][j] = -1e9f; s[3][j] = -1e9f;
            }
        }
        __syncthreads();
        float* Ps = Kt;

#pragma unroll
        for (int i = 0; i < 4; i++) {
            float mt = fmaxf(fmaxf(s[i][0], s[i][1]), fmaxf(s[i][2], s[i][3]));
#pragma unroll
            for (int off = 8; off; off >>= 1)
                mt = fmaxf(mt, __shfl_xor_sync(0xffffffffu, mt, off, 16));
            float mn = fmaxf(m_[i], mt);
            float p0 = __expf(s[i][0] - mn);
            float p1 = __expf(s[i][1] - mn);
            float p2 = __expf(s[i][2] - mn);
            float p3 = __expf(s[i][3] - mn);
            float rs = p0 + p1 + p2 + p3;
#pragma unroll
            for (int off = 8; off; off >>= 1)
                rs += __shfl_xor_sync(0xffffffffu, rs, off, 16);
            float f = __expf(m_[i] - mn);
            l_[i] = l_[i] * f + rs;
            m_[i] = mn;
#pragma unroll
            for (int j = 0; j < 4; j++) o_[i][j] *= f;
            *(float4*)(Ps + (ty*4 + i)*64 + tx*4) = make_float4(p0, p1, p2, p3);
        }
        __syncthreads();

#pragma unroll
        for (int kv = 0; kv < 64; kv++) {
            float4 vv = *(float4*)(Vs + kv*64 + tx*4);
            float vvv[4] = {vv.x, vv.y, vv.z, vv.w};
            float pv[4];
#pragma unroll
            for (int i = 0; i < 4; i++) pv[i] = Ps[(ty*4 + i)*64 + kv];
#pragma unroll
            for (int i = 0; i < 4; i++)
#pragma unroll
                for (int j = 0; j < 4; j++)
                    o_[i][j] = fmaf(pv[i], vvv[j], o_[i][j]);
        }
        __syncthreads();
    }

    const size_t obase = ((size_t)b*SEQ + (size_t)qb*64) * D_MODEL + h*DK;
#pragma unroll
    for (int i = 0; i < 4; i++) {
        float inv = 1.0f / l_[i];
        *(float4*)(ctx + obase + (size_t)(ty*4 + i)*D_MODEL + tx*4) =
            make_float4(o_[i][0]*inv, o_[i][1]*inv, o_[i][2]*inv, o_[i][3]*inv);
    }
}

// ---------------- LayerNorm (ddof=1, eps added to std) ----------------
__device__ __forceinline__ float warp_sum(float s) {
#pragma unroll
    for (int off = 16; off; off >>= 1) s += __shfl_xor_sync(0xffffffffu, s, off);
    return s;
}

__global__ __launch_bounds__(256)
void ln_kernel(const float* __restrict__ in, const float* __restrict__ alpha,
               const float* __restrict__ beta, float* __restrict__ out)
{
    __shared__ float red[8];
    const int row = blockIdx.x, tid = threadIdx.x;
    const float* rp = in + (size_t)row * D_MODEL;
    float4 v = *(const float4*)(rp + tid*4);

    float s = v.x + v.y + v.z + v.w;
    s = warp_sum(s);
    if ((tid & 31) == 0) red[tid >> 5] = s;
    __syncthreads();
    float tot = 0.f;
#pragma unroll
    for (int i = 0; i < 8; i++) tot += red[i];
    float mean = tot * (1.0f / 1024.0f);

    float dx = v.x - mean, dy = v.y - mean, dz = v.z - mean, dw = v.w - mean;
    float sq = dx*dx + dy*dy + dz*dz + dw*dw;
    __syncthreads();
    sq = warp_sum(sq);
    if ((tid & 31) == 0) red[tid >> 5] = sq;
    __syncthreads();
    float tot2 = 0.f;
#pragma unroll
    for (int i = 0; i < 8; i++) tot2 += red[i];
    float var  = tot2 * (1.0f / 1023.0f);
    float rstd = 1.0f / (sqrtf(var) + 1e-6f);

    float4 a = *(const float4*)(alpha + tid*4);
    float4 bb = *(const float4*)(beta + tid*4);
    float4 o;
    o.x = a.x * dx * rstd + bb.x;
    o.y = a.y * dy * rstd + bb.y;
    o.z = a.z * dz * rstd + bb.z;
    o.w = a.w * dw * rstd + bb.w;
    *(float4*)(out + (size_t)row * D_MODEL + tid*4) = o;
}

// ---------------- host ----------------
extern "C" void kernel_launch(void* const* d_in, const int* in_sizes, int n_in,
                              void* d_out, int out_size)
{
    const float* x      = (const float*)d_in[0];
    const int*   mask   = (const int*)  d_in[1];
    const float* wq     = (const float*)d_in[2];
    const float* wk     = (const float*)d_in[3];
    const float* wv     = (const float*)d_in[4];
    const float* wo     = (const float*)d_in[5];
    const float* wo_b   = (const float*)d_in[6];
    const float* w1     = (const float*)d_in[7];
    const float* b1     = (const float*)d_in[8];
    const float* w2     = (const float*)d_in[9];
    const float* b2     = (const float*)d_in[10];
    const float* alpha1 = (const float*)d_in[11];
    const float* bias1  = (const float*)d_in[12];
    const float* alpha2 = (const float*)d_in[13];
    const float* bias2  = (const float*)d_in[14];
    float* out = (float*)d_out;

    float *qkv, *ctx, *s1, *x1, *ff, *s2;
    __nv_bfloat16 *wqkv_hi, *wqkv_lo, *wo_hi, *wo_lo, *w1_hi, *w1_lo, *w2_hi, *w2_lo;
    cudaGetSymbolAddress((void**)&qkv, g_qkv);
    cudaGetSymbolAddress((void**)&ctx, g_ctx);
    cudaGetSymbolAddress((void**)&s1,  g_s1);
    cudaGetSymbolAddress((void**)&x1,  g_x1);
    cudaGetSymbolAddress((void**)&ff,  g_ff);
    cudaGetSymbolAddress((void**)&s2,  g_s2);
    cudaGetSymbolAddress((void**)&wqkv_hi, g_wqkv_hi);
    cudaGetSymbolAddress((void**)&wqkv_lo, g_wqkv_lo);
    cudaGetSymbolAddress((void**)&wo_hi, g_wo_hi);
    cudaGetSymbolAddress((void**)&wo_lo, g_wo_lo);
    cudaGetSymbolAddress((void**)&w1_hi, g_w1_hi);
    cudaGetSymbolAddress((void**)&w1_lo, g_w1_lo);
    cudaGetSymbolAddress((void**)&w2_hi, g_w2_hi);
    cudaGetSymbolAddress((void**)&w2_lo, g_w2_lo);

    // idempotent; no static guards allowed
    cudaFuncSetAttribute(bf16_gemm<1>, cudaFuncAttributeMaxDynamicSharedMemorySize, SMEM_G);
    cudaFuncSetAttribute(bf16_gemm<2>, cudaFuncAttributeMaxDynamicSharedMemorySize, SMEM_G);
    cudaFuncSetAttribute(bf16_gemm<3>, cudaFuncAttributeMaxDynamicSharedMemorySize, SMEM_G);

    dim3 tblk(32, 8);
    prep_w<<<dim3(D_MODEL/32, D_MODEL/32), tblk>>>(wq, wqkv_hi,                     wqkv_lo,                     D_MODEL, D_MODEL);
    prep_w<<<dim3(D_MODEL/32, D_MODEL/32), tblk>>>(wk, wqkv_hi + D_MODEL*D_MODEL,   wqkv_lo + D_MODEL*D_MODEL,   D_MODEL, D_MODEL);
    prep_w<<<dim3(D_MODEL/32, D_MODEL/32), tblk>>>(wv, wqkv_hi + 2*D_MODEL*D_MODEL, wqkv_lo + 2*D_MODEL*D_MODEL, D_MODEL, D_MODEL);
    prep_w<<<dim3(D_MODEL/32, D_MODEL/32), tblk>>>(wo, wo_hi, wo_lo, D_MODEL, D_MODEL);
    prep_w<<<dim3(DFF/32,     D_MODEL/32), tblk>>>(w1, w1_hi, w1_lo, D_MODEL, DFF);
    prep_w<<<dim3(D_MODEL/32, DFF/32),     tblk>>>(w2, w2_hi, w2_lo, DFF, D_MODEL);

    const float* q = qkv;
    const float* k = qkv + (size_t)NTOK*D_MODEL;
    const float* v = qkv + (size_t)2*NTOK*D_MODEL;

    // fused QKV projection (N=3072), head-transposed store
    bf16_gemm<1><<<dim3(24, 32), 256, SMEM_G>>>(x, wqkv_hi, wqkv_lo, qkv, nullptr, nullptr, 3*D_MODEL, D_MODEL);

    attn_kernel<<<dim3(SEQ/64, NHEADS, BATCH), 256, 3*4096*sizeof(float)>>>(q, k, v, mask, ctx);

    // O projection + residual, LN1
    bf16_gemm<2><<<dim3(8, 32), 256, SMEM_G>>>(ctx, wo_hi, wo_lo, s1, wo_b, x, D_MODEL, D_MODEL);
    ln_kernel<<<NTOK, 256>>>(s1, alpha1, bias1, x1);

    // FFN
    bf16_gemm<3><<<dim3(32, 32), 256, SMEM_G>>>(x1, w1_hi, w1_lo, ff, b1, nullptr, DFF, D_MODEL);
    bf16_gemm<2><<<dim3(8, 32), 256, SMEM_G>>>(ff, w2_hi, w2_lo, s2, b2, x1, D_MODEL, DFF);
    ln_kernel<<<NTOK, 256>>>(s2, alpha2, bias2, out);
}